// round 13
// baseline (speedup 1.0000x reference)
#include <cuda_runtime.h>
#include <cstdint>

// Problem constants (fixed-shape problem)
#define QD 50        // qubits
#define SD 64        // heads
#define SP 32        // s-pairs (SD/2), packed 2 heads per f32x2
#define HP 16        // pairs handled per thread (SP/2)
#define BT 64        // block threads
#define RPB 32       // rows per block (2 threads per row)
#define ROWF (QD*3)  // 150 floats per row (unpadded; smem mirrors gmem layout)
#define NPCTA 1480   // 148 SMs x 10 CTAs
#define MAXBLK 8192
#define EPSF 1e-12f

__device__ __align__(16) float g_headsPacked[QD * SP * 4]; // [q][pair]{h0e,h0o,h1e,h1o}
__device__ __align__(16) float g_sigma[SD * QD];           // EPS-clamp scale per (s,q)
__device__ __align__(16) float g_w[SD];                    // w_s * rho_s
__device__ float g_partials[MAXBLK];   // 2 slots per block (one per warp)
__device__ int   g_ctr  = 0;           // work-stealing cursor (reset at kernel end)
__device__ int   g_done = 0;           // completed-CTA counter (reset at kernel end)

typedef unsigned long long ull;

// -------- f32x2 packed math (sm_100+ PTX; FFMA2-class in SASS) --------
__device__ __forceinline__ ull fma2(ull a, ull b, ull c) {
    ull d;
    asm("fma.rn.f32x2 %0, %1, %2, %3;" : "=l"(d) : "l"(a), "l"(b), "l"(c));
    return d;
}
__device__ __forceinline__ ull mul2(ull a, ull b) {
    ull d;
    asm("mul.rn.f32x2 %0, %1, %2;" : "=l"(d) : "l"(a), "l"(b));
    return d;
}
__device__ __forceinline__ ull bcast2(float x) {
    ull d;
    asm("mov.b64 %0, {%1, %1};" : "=l"(d) : "f"(x));
    return d;
}
__device__ __forceinline__ float2 unpack2(ull v) {
    float2 r;
    asm("mov.b64 {%0, %1}, %2;" : "=f"(r.x), "=f"(r.y) : "l"(v));
    return r;
}
__device__ __forceinline__ float softplus20(float x) {
    float z = 20.0f * x;
    return (z > 20.0f) ? z : log1pf(expf(z));
}
// cp.async 16B with L1 bypass (.cg): streams batch data without evicting
// the L1-resident head table.
__device__ __forceinline__ void cp16(uint32_t dst_smem, const void* src) {
    asm volatile("cp.async.cg.shared.global [%0], [%1], 16;"
                 :: "r"(dst_smem), "l"(src));
}
__device__ __forceinline__ void cp_wait_all() {
    asm volatile("cp.async.commit_group;\n\tcp.async.wait_group 0;" ::: "memory");
}

// =====================================================================
// prep1: per-(s,q) softplus + L1-normalize; packed heads + sigma -> gmem.
// Math identity (exact): heads are L1-normalized over p, so
//   dot = b2 + h0*(b0-b2) + h1*(b1-b2)
// with the reference's max(sum,EPS) clamp factored out as sigma=min(1,sum/EPS).
// =====================================================================
__global__ void prep1_kernel(const float* __restrict__ hp) {
    int idx = blockIdx.x * blockDim.x + threadIdx.x;
    if (idx >= SD * QD) return;
    int s = idx / QD, q = idx - s * QD;
    const float* h = hp + (size_t)idx * 3;
    float h0 = softplus20(h[0]);
    float h1 = softplus20(h[1]);
    float h2 = softplus20(h[2]);
    float sum3 = h0 + h1 + h2;
    float sigma, g0, g1;
    if (sum3 > 0.0f) {
        sigma = fminf(1.0f, sum3 * 1e12f);
        g0 = h0 / sum3;
        g1 = h1 / sum3;
    } else {
        sigma = 0.0f; g0 = 0.0f; g1 = 0.0f;   // head contributes 0 (matches ref)
    }
    g_sigma[idx] = sigma;
    int base = (q * SP + (s >> 1)) * 4;
    int o = s & 1;
    g_headsPacked[base + o]     = g0;          // {h0_e,h0_o,h1_e,h1_o}
    g_headsPacked[base + 2 + o] = g1;
}

// prep2: head ratios (softplus, L1-norm, uniform-smooth) x rho_s -> g_w.
__global__ void prep2_kernel(const float* __restrict__ hrp) {
    __shared__ float s_sp[SD];
    __shared__ float s_tot;
    int tid = threadIdx.x;
    s_sp[tid] = softplus20(hrp[tid]);
    __syncthreads();
    if (tid == 0) {
        float t = 0.0f;
        for (int s = 0; s < SD; s++) t += s_sp[s];
        s_tot = t;
    }
    __syncthreads();
    float w = s_sp[tid] / fmaxf(s_tot, EPSF);
    w = (w + 0.001f / (float)SD) / 1.001f;
    float rho = 1.0f;
    for (int q = 0; q < QD; q++) rho *= g_sigma[tid * QD + q];
    g_w[tid] = w * rho;
}

// =====================================================================
// Main kernel. SMEM = 19.2KB dynamic only (heads now read via __ldg from
// gmem -> L1-resident 25.6KB table; cp.async.cg staging bypasses L1 so
// the streaming 60MB never evicts it). __launch_bounds__(64,10): ~102
// regs -> 10 CTAs/SM x 2 warps = 20 warps/SM (2.1x R12's occupancy).
// Compute core identical to R8/R12 (rel_err 1e-7 proven):
// 2 threads/row, 16 s-pairs each, prod[16] never spans a barrier.
// Work-stealing with per-(blk,warp) partial slots; last-finishing CTA
// sums slots in FIXED index order -> bitwise deterministic; counters
// reset for graph replay.
// =====================================================================
__global__ void __launch_bounds__(BT, 10)
main_kernel(const float* __restrict__ bp, const float* __restrict__ coeff,
            float* __restrict__ out, int N, int nblk) {
    extern __shared__ float sB[];                    // dynamic: RPB*ROWF floats (19.2KB)
    __shared__ int   s_blk;
    __shared__ int   s_last;
    __shared__ float s_red[2];
    int tid = threadIdx.x;
    int half = tid & 1;                              // which s-pair subset
    int myrow = tid >> 1;                            // row within block
    const ulonglong2* gH = (const ulonglong2*)g_headsPacked;
    const ull* gW = (const ull*)g_w;

    uint32_t sB_u32;
    {
        void* p = sB;
        sB_u32 = (uint32_t)__cvta_generic_to_shared(p);
    }

    // ---- work-stealing mainloop over 32-row blocks ----
    for (;;) {
        if (tid == 0) s_blk = atomicAdd(&g_ctr, 1);
        __syncthreads();                             // also: prev block's sB reads done
        int blk = s_blk;
        if (blk >= nblk) break;

        int n0 = blk * RPB;
        int nvalid = N - n0; if (nvalid > RPB) nvalid = RPB;
        int nf = nvalid * ROWF;

        // stage via cp.async.cg (L1 bypass); block run is 16B-aligned
        {
            const float4* src4 = (const float4*)(bp + (size_t)n0 * ROWF);
            int n4 = nf >> 2;                        // 1200 when full block
            for (int j = tid; j < n4; j += BT)
                cp16(sB_u32 + 16u * j, src4 + j);
            for (int j = (n4 << 2) + tid; j < nf; j += BT)  // tail (empty when full)
                sB[j] = bp[(size_t)n0 * ROWF + j];
            cp_wait_all();
        }
        __syncthreads();

        float contrib = 0.0f;
        if (myrow < nvalid) {
            const float* myb = sB + myrow * ROWF;
            ull prod[HP];
            #pragma unroll
            for (int i = 0; i < HP; i++) prod[i] = 0x3f8000003f800000ull; // {1,1}

            #pragma unroll 2
            for (int q = 0; q < QD; q++) {
                float b0 = myb[3 * q + 0];
                float b1 = myb[3 * q + 1];
                float b2 = myb[3 * q + 2];
                ull d0p = bcast2(b0 - b2);
                ull d1p = bcast2(b1 - b2);
                ull b2p = bcast2(b2);
                const ulonglong2* hq = gH + q * SP + half;   // pairs {2i+half}
                #pragma unroll
                for (int i = 0; i < HP; i++) {
                    ulonglong2 h = __ldg(&hq[2 * i]);  // LDG.NC.128, L1-resident
                    ull m = fma2(h.x, d0p, b2p);       // b2 + h0*(b0-b2)
                    m = fma2(h.y, d1p, m);             //    + h1*(b1-b2)
                    prod[i] = mul2(prod[i], m);        // running product over q
                }
            }

            ull acc = 0ull;
            #pragma unroll
            for (int i = 0; i < HP; i++)
                acc = fma2(prod[i], __ldg(&gW[2 * i + half]), acc);
            float2 a = unpack2(acc);
            float cov_half = a.x + a.y;                // this thread's 32 heads
            float cov = cov_half + __shfl_xor_sync(0xffffffffu, cov_half, 1);
            if (half == 0) {                           // count each row once
                float c = coeff[n0 + myrow];
                contrib = c * c / cov;
            }
        }

        // per-warp reduce; each warp owns its own partial slot
        #pragma unroll
        for (int o = 16; o > 0; o >>= 1)
            contrib += __shfl_down_sync(0xffffffffu, contrib, o);
        if ((tid & 31) == 0)
            g_partials[2 * blk + (tid >> 5)] = contrib;
    }

    // ---- last-finishing CTA does the deterministic final sum ----
    __threadfence();                                   // publish partials
    if (tid == 0) {
        int d = atomicAdd(&g_done, 1);
        s_last = (d == NPCTA - 1);
    }
    __syncthreads();
    if (s_last) {
        __threadfence();                               // see all published partials
        int nslot = 2 * nblk;
        float v = 0.0f;
        for (int i = tid; i < nslot; i += BT) v += g_partials[i];  // fixed order
        #pragma unroll
        for (int o = 16; o > 0; o >>= 1)
            v += __shfl_down_sync(0xffffffffu, v, o);
        if ((tid & 31) == 0) s_red[tid >> 5] = v;
        __syncthreads();
        if (tid == 0) {
            out[0] = s_red[0] + s_red[1];
            g_ctr  = 0;                                // restore for next replay
            g_done = 0;
        }
    }
}

extern "C" void kernel_launch(void* const* d_in, const int* in_sizes, int n_in,
                              void* d_out, int out_size) {
    const float* bp    = (const float*)d_in[0];  // batch_pauli_tensor [N,Q,3]
    const float* coeff = (const float*)d_in[1];  // batch_coeff [N]
    const float* hp    = (const float*)d_in[2];  // heads_param [S,Q,3]
    const float* hrp   = (const float*)d_in[3];  // head_ratios_param [S]
    int N = in_sizes[1];

    int nblk = (N + RPB - 1) / RPB;              // 3125 for N=100000
    if (nblk > MAXBLK / 2) nblk = MAXBLK / 2;
    int smem = RPB * ROWF * sizeof(float);       // 19,200B dynamic; total < 48KB

    prep1_kernel<<<(SD * QD + 255) / 256, 256>>>(hp);
    prep2_kernel<<<1, SD>>>(hrp);
    main_kernel<<<NPCTA, BT, smem>>>(bp, coeff, (float*)d_out, N, nblk);
}

// round 14
// speedup vs baseline: 1.1133x; 1.1133x over previous
#include <cuda_runtime.h>
#include <cstdint>

// Problem constants (fixed-shape problem)
#define QD 50        // qubits
#define SD 64        // heads
#define SP 32        // s-pairs (SD/2), packed 2 heads per f32x2
#define HP 8         // pairs handled per thread (SP/4; 4 threads per row)
#define BT 128       // block threads (4 warps share one head table)
#define RPB 32       // rows per block (4 threads per row)
#define ROWF (QD*3)  // 150 floats per row (unpadded; smem mirrors gmem layout)
#define NPCTA 740    // 148 SMs x 5 CTAs (44.8KB/CTA -> 5 co-resident, proven R12)
#define MAXBLK 16384
#define EPSF 1e-12f

__device__ float g_partials[MAXBLK];   // 4 slots per block (one per warp)
__device__ int   g_ctr  = 0;           // work-stealing cursor (reset at kernel end)
__device__ int   g_done = 0;           // completed-CTA counter (reset at kernel end)

typedef unsigned long long ull;

// -------- f32x2 packed math (sm_100+ PTX; FFMA2-class in SASS) --------
__device__ __forceinline__ ull fma2(ull a, ull b, ull c) {
    ull d;
    asm("fma.rn.f32x2 %0, %1, %2, %3;" : "=l"(d) : "l"(a), "l"(b), "l"(c));
    return d;
}
__device__ __forceinline__ ull mul2(ull a, ull b) {
    ull d;
    asm("mul.rn.f32x2 %0, %1, %2;" : "=l"(d) : "l"(a), "l"(b));
    return d;
}
__device__ __forceinline__ ull bcast2(float x) {
    ull d;
    asm("mov.b64 %0, {%1, %1};" : "=l"(d) : "f"(x));
    return d;
}
__device__ __forceinline__ float2 unpack2(ull v) {
    float2 r;
    asm("mov.b64 {%0, %1}, %2;" : "=f"(r.x), "=f"(r.y) : "l"(v));
    return r;
}
__device__ __forceinline__ float softplus20(float x) {
    float z = 20.0f * x;
    return (z > 20.0f) ? z : log1pf(expf(z));
}

// =====================================================================
// Single fused persistent kernel (only launch -> ncu profiles it).
//
// Math identity (exact): heads are L1-normalized over p, so
//   dot = b2 + h0*(b0-b2) + h1*(b1-b2)
// with the reference's max(sum,EPS) clamp factored out as a per-(s,q)
// scale sigma = min(1, sum/EPS) whose product rho_s is folded into the
// head-ratio weight w_s.
//
// R14 change vs R12: 4 warps/CTA (BT=128) sharing one 25.6KB smem head
// table; 4 threads per row, each owning 8 interleaved s-pairs
// {sub + 4i}. Same total smem/CTA (~45KB) -> still 5 CTAs/SM, but 20
// warps/SM instead of 10 (R12 profile showed occupancy/latency bound:
// occ 14.6%, issue 35%, fma 31%). Heads stay in smem (R13 proved LDG
// heads are LSU-bound: 117us).
//
// Determinism: g_partials[4*blk+warp] depends only on (blk,warp); the
// last-finishing CTA sums slots in FIXED index order; counters reset
// for graph replay.
// =====================================================================
__global__ void __launch_bounds__(BT, 5)
main_kernel(const float* __restrict__ bp, const float* __restrict__ coeff,
            const float* __restrict__ hp, const float* __restrict__ hrp,
            float* __restrict__ out, int N, int nblk) {
    extern __shared__ float sB[];                    // dynamic: RPB*ROWF floats (19.2KB)
    __shared__ ulonglong2 sH[QD * SP];               // 25.6KB packed heads [q][pair]{h0p,h1p}
    __shared__ __align__(16) float sWf[SD];          // w_s * rho_s (read as ull pairs)
    __shared__ float s_sp[SD];
    __shared__ float s_tot;
    __shared__ int   s_blk;
    __shared__ int   s_last;
    __shared__ float s_red[4];
    int tid = threadIdx.x;
    float* sHf = (float*)sH;

    // ---- Phase A: softplus + L1-normalize heads; sigma parked in sB ----
    for (int idx = tid; idx < SD * QD; idx += BT) {
        int s = idx / QD, q = idx - s * QD;
        const float* h = hp + (size_t)(s * QD + q) * 3;
        float h0 = softplus20(h[0]);
        float h1 = softplus20(h[1]);
        float h2 = softplus20(h[2]);
        float sum3 = h0 + h1 + h2;
        float sigma, g0, g1;
        if (sum3 > 0.0f) {
            sigma = fminf(1.0f, sum3 * 1e12f);
            g0 = h0 / sum3;
            g1 = h1 / sum3;
        } else {
            sigma = 0.0f; g0 = 0.0f; g1 = 0.0f;       // head contributes 0 (matches ref)
        }
        sB[idx] = sigma;                               // temp use of dynamic smem (12.8KB)
        int base = (q * SP + (s >> 1)) * 4;
        int o = s & 1;
        sHf[base + o]     = g0;                        // {h0_e,h0_o,h1_e,h1_o}
        sHf[base + 2 + o] = g1;
    }
    if (tid < SD) s_sp[tid] = softplus20(hrp[tid]);
    __syncthreads();
    if (tid == 0) {
        float t = 0.0f;
        for (int s = 0; s < SD; s++) t += s_sp[s];
        s_tot = t;
    }
    __syncthreads();
    if (tid < SD) {
        float w = s_sp[tid] / fmaxf(s_tot, EPSF);
        w = (w + 0.001f / (float)SD) / 1.001f;
        float rho = 1.0f;
        for (int q = 0; q < QD; q++) rho *= sB[tid * QD + q];
        sWf[tid] = w * rho;
    }
    const ull* sW = (const ull*)sWf;

    int sub = tid & 3;                                 // which s-pair subset (of 4)
    int myrow = tid >> 2;                              // row within block (0..31)

    // ---- Phase B: work-stealing mainloop over 32-row blocks ----
    for (;;) {
        if (tid == 0) s_blk = atomicAdd(&g_ctr, 1);
        __syncthreads();                               // also: prev block's sB reads done
        int blk = s_blk;
        if (blk >= nblk) break;

        int n0 = blk * RPB;
        int nvalid = N - n0; if (nvalid > RPB) nvalid = RPB;
        int nf = nvalid * ROWF;

        // stage: contiguous gmem run; 19200*blk bytes is always 16B-aligned
        {
            const float4* src4 = (const float4*)(bp + (size_t)n0 * ROWF);
            float4* dst4 = (float4*)sB;
            int n4 = nf >> 2;                          // 1200 when full block
            for (int j = tid; j < n4; j += BT) dst4[j] = src4[j];
            for (int j = (n4 << 2) + tid; j < nf; j += BT)   // tail (empty when full)
                sB[j] = bp[(size_t)n0 * ROWF + j];
        }
        __syncthreads();

        float contrib = 0.0f;
        if (myrow < nvalid) {
            const float* myb = sB + myrow * ROWF;
            ull prod[HP];
            #pragma unroll
            for (int i = 0; i < HP; i++) prod[i] = 0x3f8000003f800000ull; // {1,1}

            #pragma unroll 2
            for (int q = 0; q < QD; q++) {
                float b0 = myb[3 * q + 0];
                float b1 = myb[3 * q + 1];
                float b2 = myb[3 * q + 2];
                ull d0p = bcast2(b0 - b2);
                ull d1p = bcast2(b1 - b2);
                ull b2p = bcast2(b2);
                const ulonglong2* hq = sH + q * SP + sub;    // pairs {4i+sub}
                #pragma unroll
                for (int i = 0; i < HP; i++) {
                    ulonglong2 h = hq[4 * i];          // LDS.128: 4 contig addrs, 1 phase
                    ull m = fma2(h.x, d0p, b2p);       // b2 + h0*(b0-b2)
                    m = fma2(h.y, d1p, m);             //    + h1*(b1-b2)
                    prod[i] = mul2(prod[i], m);        // running product over q
                }
            }

            ull acc = 0ull;
            #pragma unroll
            for (int i = 0; i < HP; i++) acc = fma2(prod[i], sW[4 * i + sub], acc);
            float2 a = unpack2(acc);
            float cq = a.x + a.y;                      // this thread's 16 heads
            cq += __shfl_xor_sync(0xffffffffu, cq, 1); // combine 4 subsets
            cq += __shfl_xor_sync(0xffffffffu, cq, 2);
            if (sub == 0) {                            // count each row once
                float c = coeff[n0 + myrow];
                contrib = c * c / cq;
            }
        }

        // per-warp reduce; each warp owns its own partial slot
        #pragma unroll
        for (int o = 16; o > 0; o >>= 1)
            contrib += __shfl_down_sync(0xffffffffu, contrib, o);
        if ((tid & 31) == 0)
            g_partials[4 * blk + (tid >> 5)] = contrib;
    }

    // ---- last-finishing CTA does the deterministic final sum ----
    __threadfence();                                   // publish partials
    if (tid == 0) {
        int d = atomicAdd(&g_done, 1);
        s_last = (d == NPCTA - 1);
    }
    __syncthreads();
    if (s_last) {
        __threadfence();                               // see all published partials
        int nslot = 4 * nblk;
        float v = 0.0f;
        for (int i = tid; i < nslot; i += BT) v += g_partials[i];  // fixed order
        #pragma unroll
        for (int o = 16; o > 0; o >>= 1)
            v += __shfl_down_sync(0xffffffffu, v, o);
        if ((tid & 31) == 0) s_red[tid >> 5] = v;
        __syncthreads();
        if (tid == 0) {
            out[0] = (s_red[0] + s_red[1]) + (s_red[2] + s_red[3]);
            g_ctr  = 0;                                // restore for next replay
            g_done = 0;
        }
    }
}

extern "C" void kernel_launch(void* const* d_in, const int* in_sizes, int n_in,
                              void* d_out, int out_size) {
    const float* bp    = (const float*)d_in[0];  // batch_pauli_tensor [N,Q,3]
    const float* coeff = (const float*)d_in[1];  // batch_coeff [N]
    const float* hp    = (const float*)d_in[2];  // heads_param [S,Q,3]
    const float* hrp   = (const float*)d_in[3];  // head_ratios_param [S]
    int N = in_sizes[1];

    int nblk = (N + RPB - 1) / RPB;              // 3125 for N=100000
    if (nblk > MAXBLK / 4) nblk = MAXBLK / 4;
    int smem = RPB * ROWF * sizeof(float);       // 19,200B dynamic; total < 48KB

    main_kernel<<<NPCTA, BT, smem>>>(bp, coeff, hp, hrp, (float*)d_out, N, nblk);
}

// round 16
// speedup vs baseline: 1.3555x; 1.2175x over previous
#include <cuda_runtime.h>
#include <cstdint>

// Problem constants (fixed-shape problem)
#define QD 50        // qubits
#define SD 64        // heads
#define SP 32        // s-pairs (SD/2), packed 2 heads per f32x2
#define P_PAIRS 4    // pairs per thread (8 threads per row)
#define R_ROWS 4     // rows per thread (head loads amortized over 4 rows)
#define BT 64        // block threads
#define RPB 32       // rows per block
#define ROWF (QD*3)  // 150 floats per row (unpadded; smem mirrors gmem layout)
#define NPCTA 740    // 148 SMs x 5 CTAs (44.8KB/CTA)
#define MAXBLK 8192
#define EPSF 1e-12f

__device__ float g_partials[MAXBLK];   // 2 slots per block (one per warp)
__device__ int   g_ctr  = 0;           // work-stealing cursor (reset at kernel end)
__device__ int   g_done = 0;           // completed-CTA counter (reset at kernel end)

typedef unsigned long long ull;

// -------- f32x2 packed math (sm_100+ PTX; FFMA2-class in SASS) --------
__device__ __forceinline__ ull fma2(ull a, ull b, ull c) {
    ull d;
    asm("fma.rn.f32x2 %0, %1, %2, %3;" : "=l"(d) : "l"(a), "l"(b), "l"(c));
    return d;
}
__device__ __forceinline__ ull mul2(ull a, ull b) {
    ull d;
    asm("mul.rn.f32x2 %0, %1, %2;" : "=l"(d) : "l"(a), "l"(b));
    return d;
}
__device__ __forceinline__ ull bcast2(float x) {
    ull d;
    asm("mov.b64 %0, {%1, %1};" : "=l"(d) : "f"(x));
    return d;
}
__device__ __forceinline__ float2 unpack2(ull v) {
    float2 r;
    asm("mov.b64 {%0, %1}, %2;" : "=f"(r.x), "=f"(r.y) : "l"(v));
    return r;
}
__device__ __forceinline__ float softplus20(float x) {
    float z = 20.0f * x;
    return (z > 20.0f) ? z : log1pf(expf(z));
}

// =====================================================================
// Single fused persistent kernel.
//
// Math identity (exact): heads are L1-normalized over p, so
//   dot = b2 + h0*(b0-b2) + h1*(b1-b2)
// with the reference's max(sum,EPS) clamp factored out as a per-(s,q)
// scale sigma = min(1, sum/EPS) whose product rho_s is folded into the
// head-ratio weight w_s.
//
// R15 change vs R12/R14: the kernel was smem-WAVEFRONT bound (R14: L1
// 76.6%, issue flat despite 2x occupancy). Each thread now carries
// R_ROWS=4 rows x P_PAIRS=4 head pairs, so each 16B head load (4 smem
// wavefronts) is reused across 4 rows: head traffic per row*q drops 4x
// (4.375 -> 1.75 wf/row*q). Accumulators prod[4][4] = 32 regs, still
// barrier-free (full 32-row staging as in R12 -> no R2-style spills).
// Heads stay in smem (R13 proved LDG heads are LSU-bound).
//
// Determinism: g_partials[2*blk+warp] depends only on (blk,warp); the
// last-finishing CTA sums slots in FIXED index order; counters reset
// for graph replay.
// =====================================================================
__global__ void __launch_bounds__(BT, 5)
main_kernel(const float* __restrict__ bp, const float* __restrict__ coeff,
            const float* __restrict__ hp, const float* __restrict__ hrp,
            float* __restrict__ out, int N, int nblk) {
    extern __shared__ float sB[];                    // dynamic: RPB*ROWF floats (19.2KB)
    __shared__ ulonglong2 sH[QD * SP];               // 25.6KB packed heads [q][pair]{h0p,h1p}
    __shared__ __align__(16) float sWf[SD];          // w_s * rho_s (read as ull pairs)
    __shared__ float s_sp[SD];
    __shared__ float s_tot;
    __shared__ int   s_blk;
    __shared__ int   s_last;
    __shared__ float s_red[2];
    int tid = threadIdx.x;
    float* sHf = (float*)sH;

    // ---- Phase A: softplus + L1-normalize heads; sigma parked in sB ----
    for (int idx = tid; idx < SD * QD; idx += BT) {
        int s = idx / QD, q = idx - s * QD;
        const float* h = hp + (size_t)(s * QD + q) * 3;
        float h0 = softplus20(h[0]);
        float h1 = softplus20(h[1]);
        float h2 = softplus20(h[2]);
        float sum3 = h0 + h1 + h2;
        float sigma, g0, g1;
        if (sum3 > 0.0f) {
            sigma = fminf(1.0f, sum3 * 1e12f);
            g0 = h0 / sum3;
            g1 = h1 / sum3;
        } else {
            sigma = 0.0f; g0 = 0.0f; g1 = 0.0f;       // head contributes 0 (matches ref)
        }
        sB[idx] = sigma;                               // temp use of dynamic smem
        int base = (q * SP + (s >> 1)) * 4;
        int o = s & 1;
        sHf[base + o]     = g0;                        // {h0_e,h0_o,h1_e,h1_o}
        sHf[base + 2 + o] = g1;
    }
    s_sp[tid] = softplus20(hrp[tid]);                  // BT == SD == 64
    __syncthreads();
    if (tid == 0) {
        float t = 0.0f;
        for (int s = 0; s < SD; s++) t += s_sp[s];
        s_tot = t;
    }
    __syncthreads();
    {
        float w = s_sp[tid] / fmaxf(s_tot, EPSF);
        w = (w + 0.001f / (float)SD) / 1.001f;
        float rho = 1.0f;
        for (int q = 0; q < QD; q++) rho *= sB[tid * QD + q];
        sWf[tid] = w * rho;
    }
    const ull* sW = (const ull*)sWf;

    int sub  = tid & 7;                                // pair subset: owns {8i+sub}
    int rowg = tid >> 3;                               // row group (0..7); rows rowg+8j

    // ---- Phase B: work-stealing mainloop over 32-row blocks ----
    for (;;) {
        if (tid == 0) s_blk = atomicAdd(&g_ctr, 1);
        __syncthreads();                               // also: prev block's sB reads done
        int blk = s_blk;
        if (blk >= nblk) break;

        int n0 = blk * RPB;
        int nvalid = N - n0; if (nvalid > RPB) nvalid = RPB;
        int nf = nvalid * ROWF;

        // stage: contiguous gmem run; 19200*blk bytes is always 16B-aligned.
        // Zero-fill the tail region so partial blocks read clean zeros.
        {
            const float4* src4 = (const float4*)(bp + (size_t)n0 * ROWF);
            float4* dst4 = (float4*)sB;
            int n4 = nf >> 2;                          // 1200 when full block
            for (int j = tid; j < n4; j += BT) dst4[j] = src4[j];
            for (int j = (n4 << 2) + tid; j < RPB * ROWF; j += BT)
                sB[j] = (j < nf) ? bp[(size_t)n0 * ROWF + j] : 0.0f;
        }
        __syncthreads();

        ull prod[R_ROWS][P_PAIRS];
        #pragma unroll
        for (int j = 0; j < R_ROWS; j++)
            #pragma unroll
            for (int i = 0; i < P_PAIRS; i++)
                prod[j][i] = 0x3f8000003f800000ull;    // {1.f, 1.f}

        #pragma unroll 2
        for (int q = 0; q < QD; q++) {
            // per-row packed operands (loads amortize heads across 4 rows)
            ull d0p[R_ROWS], d1p[R_ROWS], b2p[R_ROWS];
            #pragma unroll
            for (int j = 0; j < R_ROWS; j++) {
                const float* myb = sB + (rowg + 8 * j) * ROWF + 3 * q;
                float b0 = myb[0], b1 = myb[1], b2 = myb[2];
                d0p[j] = bcast2(b0 - b2);
                d1p[j] = bcast2(b1 - b2);
                b2p[j] = bcast2(b2);
            }
            const ulonglong2* hq = sH + q * SP + sub;  // pairs {8i+sub}
            #pragma unroll
            for (int i = 0; i < P_PAIRS; i++) {
                ulonglong2 h = hq[8 * i];              // LDS.128, reused by 4 rows
                #pragma unroll
                for (int j = 0; j < R_ROWS; j++) {
                    ull m = fma2(h.x, d0p[j], b2p[j]); // b2 + h0*(b0-b2)
                    m = fma2(h.y, d1p[j], m);          //    + h1*(b1-b2)
                    prod[j][i] = mul2(prod[j][i], m);  // running product over q
                }
            }
        }

        // combine: per-row cov over this thread's 8 heads, then across subs
        float contrib = 0.0f;
        #pragma unroll
        for (int j = 0; j < R_ROWS; j++) {
            ull acc = 0ull;
            #pragma unroll
            for (int i = 0; i < P_PAIRS; i++)
                acc = fma2(prod[j][i], sW[8 * i + sub], acc);
            float2 a = unpack2(acc);
            float cq = a.x + a.y;
            cq += __shfl_xor_sync(0xffffffffu, cq, 1); // combine 8 subsets
            cq += __shfl_xor_sync(0xffffffffu, cq, 2);
            cq += __shfl_xor_sync(0xffffffffu, cq, 4);
            int row = rowg + 8 * j;
            if (sub == 0 && row < nvalid) {
                float c = coeff[n0 + row];
                contrib += c * c / cq;
            }
        }

        // per-warp reduce; each warp owns its own partial slot
        #pragma unroll
        for (int o = 16; o > 0; o >>= 1)
            contrib += __shfl_down_sync(0xffffffffu, contrib, o);
        if ((tid & 31) == 0)
            g_partials[2 * blk + (tid >> 5)] = contrib;
    }

    // ---- last-finishing CTA does the deterministic final sum ----
    __threadfence();                                   // publish partials
    if (tid == 0) {
        int d = atomicAdd(&g_done, 1);
        s_last = (d == NPCTA - 1);
    }
    __syncthreads();
    if (s_last) {
        __threadfence();                               // see all published partials
        int nslot = 2 * nblk;
        float v = 0.0f;
        for (int i = tid; i < nslot; i += BT) v += g_partials[i];  // fixed order
        #pragma unroll
        for (int o = 16; o > 0; o >>= 1)
            v += __shfl_down_sync(0xffffffffu, v, o);
        if ((tid & 31) == 0) s_red[tid >> 5] = v;
        __syncthreads();
        if (tid == 0) {
            out[0] = s_red[0] + s_red[1];
            g_ctr  = 0;                                // restore for next replay
            g_done = 0;
        }
    }
}

extern "C" void kernel_launch(void* const* d_in, const int* in_sizes, int n_in,
                              void* d_out, int out_size) {
    const float* bp    = (const float*)d_in[0];  // batch_pauli_tensor [N,Q,3]
    const float* coeff = (const float*)d_in[1];  // batch_coeff [N]
    const float* hp    = (const float*)d_in[2];  // heads_param [S,Q,3]
    const float* hrp   = (const float*)d_in[3];  // head_ratios_param [S]
    int N = in_sizes[1];

    int nblk = (N + RPB - 1) / RPB;              // 3125 for N=100000
    if (nblk > MAXBLK / 2) nblk = MAXBLK / 2;
    int smem = RPB * ROWF * sizeof(float);       // 19,200B dynamic; total < 48KB

    main_kernel<<<NPCTA, BT, smem>>>(bp, coeff, hp, hrp, (float*)d_out, N, nblk);
}